// round 14
// baseline (speedup 1.0000x reference)
#include <cuda_runtime.h>
#include <cuda_fp16.h>

#define MAXN 200000
#define MAXE 6500000

// Scratch (device globals — no runtime allocation allowed)
// g_cnt zero on first call (static init); re-zeroed by k_final every call.
__device__ int      g_cnt[MAXN];        // in-degree (without self loop)
__device__ int      g_rowptr[MAXN];     // CSR row start
__device__ int      g_bsums[256];       // block sums for scan
__device__ int      g_csr[MAXE];        // src indices grouped by dst (compact)
__device__ unsigned g_rankpack[MAXE];   // (rank << 18) | dst per edge
__device__ float    g_dinv[MAXN];
__device__ __half   g_hs1h[MAXN * 16];  // layer-1 scaled features (fp16)
__device__ __half   g_hs2h[MAXN * 16];  // layer-2 scaled features (fp16)
__device__ float4   g_t1[MAXN * 4];     // layer-1 neighbor sums (fp32)
__device__ float4   g_t2[MAXN * 4];     // layer-2 neighbor sums

// ---------------------------------------------------------------------------
// count: cnt[dst]++ per edge; rank (atomic return) packed with dst, stored
// as uint4. 8 edges per thread (2x int4 loads) for MLP.
// ---------------------------------------------------------------------------
__global__ void k_count(const int* __restrict__ dst, int E) {
    int t = threadIdx.x;
    const int4* d4 = (const int4*)dst;
    int nv4 = E >> 2;
#pragma unroll
    for (int q = 0; q < 2; q++) {
        int i4 = blockIdx.x * 512 + q * 256 + t;
        if (i4 < nv4) {
            int4 v = __ldg(d4 + i4);
            int r0 = atomicAdd(&g_cnt[v.x], 1);
            int r1 = atomicAdd(&g_cnt[v.y], 1);
            int r2 = atomicAdd(&g_cnt[v.z], 1);
            int r3 = atomicAdd(&g_cnt[v.w], 1);
            uint4 p;
            p.x = ((unsigned)r0 << 18) | (unsigned)v.x;
            p.y = ((unsigned)r1 << 18) | (unsigned)v.y;
            p.z = ((unsigned)r2 << 18) | (unsigned)v.z;
            p.w = ((unsigned)r3 << 18) | (unsigned)v.w;
            ((uint4*)g_rankpack)[i4] = p;
        }
    }
    if (blockIdx.x == 0 && t < (E & 3)) {
        int e = nv4 * 4 + t;
        int d = __ldg(dst + e);
        int r = atomicAdd(&g_cnt[d], 1);
        g_rankpack[e] = ((unsigned)r << 18) | (unsigned)d;
    }
}

// scan part 1: per-block (1024 elements) sums
__global__ void k_scan1(int n) {
    __shared__ int sh[256];
    int b = blockIdx.x, t = threadIdx.x;
    int i0 = b * 1024 + t * 4;
    int s = 0;
#pragma unroll
    for (int k = 0; k < 4; k++) { int i = i0 + k; if (i < n) s += g_cnt[i]; }
    sh[t] = s; __syncthreads();
    for (int off = 128; off > 0; off >>= 1) {
        if (t < off) sh[t] += sh[t + off];
        __syncthreads();
    }
    if (t == 0) g_bsums[b] = sh[0];
}

// scan part 2: every block redundantly scans block sums, then its chunk;
// also writes dinv.
__global__ void k_scan23(int n, int nb) {
    __shared__ int bs[256];
    __shared__ int sh[256];
    int b = blockIdx.x, t = threadIdx.x;

    int v = (t < nb) ? g_bsums[t] : 0;
    bs[t] = v; __syncthreads();
    for (int off = 1; off < 256; off <<= 1) {
        int a = (t >= off) ? bs[t - off] : 0;
        __syncthreads();
        bs[t] += a;
        __syncthreads();
    }
    int blockoff = (b > 0) ? bs[b - 1] : 0;

    int i0 = b * 1024 + t * 4;
    int c[4]; int s = 0;
#pragma unroll
    for (int k = 0; k < 4; k++) { int i = i0 + k; c[k] = (i < n) ? g_cnt[i] : 0; s += c[k]; }
    int tot = s;
    sh[t] = tot; __syncthreads();
    for (int off = 1; off < 256; off <<= 1) {
        int a = (t >= off) ? sh[t - off] : 0;
        __syncthreads();
        sh[t] += a;
        __syncthreads();
    }
    int run = sh[t] - tot + blockoff;
#pragma unroll
    for (int k = 0; k < 4; k++) {
        int i = i0 + k;
        if (i < n) {
            g_rowptr[i] = run; run += c[k];
            g_dinv[i] = rsqrtf((float)c[k] + 1.0f);
        }
    }
}

// ---------------------------------------------------------------------------
// GEMM1 standalone: thread-per-node, hs1 = (x @ W1) * dinv -> fp16. 8KB smem.
// ---------------------------------------------------------------------------
__global__ void k_gemm(const float* __restrict__ x, const float* __restrict__ W1, int n) {
    __shared__ float4 Ws[512];            // W1: 128x16 f32 = 8KB
    int t = threadIdx.x;                  // 256 threads

    {
        const float4* W4 = (const float4*)W1;
        for (int i = t; i < 512; i += 256) Ws[i] = W4[i];
    }
    __syncthreads();

    int node = blockIdx.x * 256 + t;
    if (node >= n) return;

    float acc[16];
#pragma unroll
    for (int q = 0; q < 16; q++) acc[q] = 0.f;

    const float4* xr = (const float4*)x + (size_t)node * 32;
#pragma unroll 8
    for (int k4 = 0; k4 < 32; k4++) {
        float4 xv = __ldg(xr + k4);
        float xj[4] = {xv.x, xv.y, xv.z, xv.w};
#pragma unroll
        for (int j = 0; j < 4; j++) {
            int k = k4 * 4 + j;
            float4 w0 = Ws[k * 4 + 0];
            float4 w1 = Ws[k * 4 + 1];
            float4 w2 = Ws[k * 4 + 2];
            float4 w3 = Ws[k * 4 + 3];
            float v = xj[j];
            acc[0]  += v * w0.x; acc[1]  += v * w0.y; acc[2]  += v * w0.z; acc[3]  += v * w0.w;
            acc[4]  += v * w1.x; acc[5]  += v * w1.y; acc[6]  += v * w1.z; acc[7]  += v * w1.w;
            acc[8]  += v * w2.x; acc[9]  += v * w2.y; acc[10] += v * w2.z; acc[11] += v * w2.w;
            acc[12] += v * w3.x; acc[13] += v * w3.y; acc[14] += v * w3.z; acc[15] += v * w3.w;
        }
    }
    float di = g_dinv[node];
    __half2* o = (__half2*)(g_hs1h + node * 16);
#pragma unroll
    for (int q = 0; q < 8; q++)
        o[q] = __float22half2_rn(make_float2(acc[2 * q] * di, acc[2 * q + 1] * di));
}

// ---------------------------------------------------------------------------
// fill: pos = rowptr[d] + rank  (NO atomics, low regs, high occupancy)
// ---------------------------------------------------------------------------
__global__ void k_fill(const int* __restrict__ src, int E) {
    int e = blockIdx.x * blockDim.x + threadIdx.x;
    if (e >= E) return;
    unsigned code = g_rankpack[e];
    int d = (int)(code & 0x3FFFFu);
    int rank = (int)(code >> 18);
    int pos = __ldg(g_rowptr + d) + rank;
    g_csr[pos] = __ldg(src + e);
}

// ---------------------------------------------------------------------------
// gather pass: 4 threads per node, 4 channels each via uint2, 8-deep batching.
// ---------------------------------------------------------------------------
__global__ void k_gather(int n, int layer) {
    int gid = blockIdx.x * blockDim.x + threadIdx.x;
    int node = gid >> 2;
    int sub  = gid & 3;
    if (node >= n) return;
    const uint2* hs = (const uint2*)(layer ? g_hs2h : g_hs1h);
    float4* tt = layer ? g_t2 : g_t1;

    int row = g_rowptr[node];
    int cnt = g_cnt[node];
    const int* cs = g_csr + row;

    float a0 = 0.f, a1 = 0.f, a2 = 0.f, a3 = 0.f;
    int j = 0;
    for (; j + 8 <= cnt; j += 8) {
        int s[8];
#pragma unroll
        for (int q = 0; q < 8; q++) s[q] = __ldg(cs + j + q);
        uint2 u[8];
#pragma unroll
        for (int q = 0; q < 8; q++) u[q] = __ldg(hs + s[q] * 4 + sub);
#pragma unroll
        for (int q = 0; q < 8; q++) {
            float2 f = __half22float2(*(const __half2*)&u[q].x);
            float2 g = __half22float2(*(const __half2*)&u[q].y);
            a0 += f.x; a1 += f.y; a2 += g.x; a3 += g.y;
        }
    }
    for (; j < cnt; j++) {
        int s = __ldg(cs + j);
        uint2 u = __ldg(hs + s * 4 + sub);
        float2 f = __half22float2(*(const __half2*)&u.x);
        float2 g = __half22float2(*(const __half2*)&u.y);
        a0 += f.x; a1 += f.y; a2 += g.x; a3 += g.y;
    }
    tt[node * 4 + sub] = make_float4(a0, a1, a2, a3);
}

// ---------------------------------------------------------------------------
// combine: h1 = relu(dinv*(t1+hs1)+b1); hs2 = (h1 @ W2)*dinv -> fp16.
// ---------------------------------------------------------------------------
__global__ void k_combine(const float* __restrict__ W2, const float* __restrict__ b1, int n) {
    __shared__ float W2s[256];
    __shared__ float b1s[16];
    int t = threadIdx.x;
    if (t < 256) W2s[t] = W2[t];
    if (t < 16)  b1s[t] = b1[t];
    __syncthreads();

    int i = blockIdx.x * blockDim.x + threadIdx.x;
    if (i >= n) return;
    float di = g_dinv[i];

    float h1[16];
#pragma unroll
    for (int q = 0; q < 4; q++) {
        float4 tv = g_t1[i * 4 + q];
        float2 s0 = __half22float2(((const __half2*)g_hs1h)[i * 8 + q * 2 + 0]);
        float2 s1 = __half22float2(((const __half2*)g_hs1h)[i * 8 + q * 2 + 1]);
        float v;
        v = di * (tv.x + s0.x) + b1s[q * 4 + 0]; h1[q * 4 + 0] = v > 0.f ? v : 0.f;
        v = di * (tv.y + s0.y) + b1s[q * 4 + 1]; h1[q * 4 + 1] = v > 0.f ? v : 0.f;
        v = di * (tv.z + s1.x) + b1s[q * 4 + 2]; h1[q * 4 + 2] = v > 0.f ? v : 0.f;
        v = di * (tv.w + s1.y) + b1s[q * 4 + 3]; h1[q * 4 + 3] = v > 0.f ? v : 0.f;
    }
#pragma unroll
    for (int q = 0; q < 4; q++) {
        float a0 = 0.f, a1 = 0.f, a2 = 0.f, a3 = 0.f;
#pragma unroll
        for (int k = 0; k < 16; k++) {
            float hv = h1[k];
            a0 += hv * W2s[k * 16 + q * 4 + 0];
            a1 += hv * W2s[k * 16 + q * 4 + 1];
            a2 += hv * W2s[k * 16 + q * 4 + 2];
            a3 += hv * W2s[k * 16 + q * 4 + 3];
        }
        ((__half2*)g_hs2h)[i * 8 + q * 2 + 0] = __float22half2_rn(make_float2(a0 * di, a1 * di));
        ((__half2*)g_hs2h)[i * 8 + q * 2 + 1] = __float22half2_rn(make_float2(a2 * di, a3 * di));
    }
}

// ---------------------------------------------------------------------------
// final: h2 = relu(dinv*(t2+hs2)+b2); GRU (h0=0 => gh=b_hh); out = h'@Wfc.T+bfc
// Also re-zeroes g_cnt for the next kernel_launch call.
// ---------------------------------------------------------------------------
__device__ __forceinline__ float sigmoidf_(float x) { return 1.0f / (1.0f + expf(-x)); }

__global__ void k_final(const float* __restrict__ b2,
                        const float* __restrict__ w_ih, const float* __restrict__ b_ih,
                        const float* __restrict__ b_hh,
                        const float* __restrict__ Wfc, const float* __restrict__ bfc,
                        float* __restrict__ out, int n) {
    __shared__ float wihs[768];
    __shared__ float wfcs[512];
    __shared__ float bihs[48];
    __shared__ float bhhs[48];
    __shared__ float bfcs[32];
    __shared__ float b2s[16];
    int t = threadIdx.x;
    for (int i = t; i < 768; i += blockDim.x) wihs[i] = w_ih[i];
    for (int i = t; i < 512; i += blockDim.x) wfcs[i] = Wfc[i];
    if (t < 48) { bihs[t] = b_ih[t]; bhhs[t] = b_hh[t]; }
    if (t < 32) bfcs[t] = bfc[t];
    if (t < 16) b2s[t] = b2[t];
    __syncthreads();

    int i = blockIdx.x * blockDim.x + threadIdx.x;
    if (i >= n) return;
    g_cnt[i] = 0;                      // reset for next call
    float di = g_dinv[i];

    float h2[16];
#pragma unroll
    for (int q = 0; q < 4; q++) {
        float4 tv = g_t2[i * 4 + q];
        float2 s0 = __half22float2(((const __half2*)g_hs2h)[i * 8 + q * 2 + 0]);
        float2 s1 = __half22float2(((const __half2*)g_hs2h)[i * 8 + q * 2 + 1]);
        float v;
        v = di * (tv.x + s0.x) + b2s[q * 4 + 0]; h2[q * 4 + 0] = v > 0.f ? v : 0.f;
        v = di * (tv.y + s0.y) + b2s[q * 4 + 1]; h2[q * 4 + 1] = v > 0.f ? v : 0.f;
        v = di * (tv.z + s1.x) + b2s[q * 4 + 2]; h2[q * 4 + 2] = v > 0.f ? v : 0.f;
        v = di * (tv.w + s1.y) + b2s[q * 4 + 3]; h2[q * 4 + 3] = v > 0.f ? v : 0.f;
    }

    float hout[16];
#pragma unroll
    for (int k = 0; k < 16; k++) {
        float ar = bihs[k], az = bihs[16 + k], an = bihs[32 + k];
#pragma unroll
        for (int c = 0; c < 16; c++) {
            float hv = h2[c];
            ar += hv * wihs[k * 16 + c];
            az += hv * wihs[(16 + k) * 16 + c];
            an += hv * wihs[(32 + k) * 16 + c];
        }
        float r = sigmoidf_(ar + bhhs[k]);
        float z = sigmoidf_(az + bhhs[16 + k]);
        float nn = tanhf(an + r * bhhs[32 + k]);
        hout[k] = (1.0f - z) * nn;
    }

    float4* outp = (float4*)(out + (size_t)i * 32);
#pragma unroll
    for (int q = 0; q < 8; q++) {
        float4 o;
        float a0 = bfcs[q * 4 + 0], a1 = bfcs[q * 4 + 1];
        float a2 = bfcs[q * 4 + 2], a3 = bfcs[q * 4 + 3];
#pragma unroll
        for (int k = 0; k < 16; k++) {
            float hv = hout[k];
            a0 += hv * wfcs[(q * 4 + 0) * 16 + k];
            a1 += hv * wfcs[(q * 4 + 1) * 16 + k];
            a2 += hv * wfcs[(q * 4 + 2) * 16 + k];
            a3 += hv * wfcs[(q * 4 + 3) * 16 + k];
        }
        o.x = a0; o.y = a1; o.z = a2; o.w = a3;
        outp[q] = o;
    }
}

// ---------------------------------------------------------------------------
extern "C" void kernel_launch(void* const* d_in, const int* in_sizes, int n_in,
                              void* d_out, int out_size) {
    const float* x    = (const float*)d_in[0];
    const int*   ei   = (const int*)  d_in[1];
    const float* W1   = (const float*)d_in[3];
    const float* b1   = (const float*)d_in[4];
    const float* W2   = (const float*)d_in[5];
    const float* b2   = (const float*)d_in[6];
    const float* w_ih = (const float*)d_in[7];
    const float* b_ih = (const float*)d_in[9];
    const float* b_hh = (const float*)d_in[10];
    const float* Wfc  = (const float*)d_in[11];
    const float* bfc  = (const float*)d_in[12];
    float* out = (float*)d_out;

    int n = in_sizes[2];           // N nodes
    int E = in_sizes[1] / 2;       // edges
    const int* src = ei;
    const int* dst = ei + E;

    int nv4 = E >> 2;
    int ncount = (nv4 + 511) / 512;
    int nb     = (n + 1023) / 1024;          // scan blocks (<=256)
    int ngemm  = (n + 255) / 256;

    k_count<<<ncount, 256>>>(dst, E);                            // 1
    k_scan1<<<nb, 256>>>(n);                                     // 2
    k_scan23<<<nb, 256>>>(n, nb);                                // 3
    k_gemm<<<ngemm, 256>>>(x, W1, n);                            // 4: PROFILED
    k_fill<<<(E + 255) / 256, 256>>>(src, E);                    // 5

    int n4 = n * 4;
    k_gather<<<(n4 + 255) / 256, 256>>>(n, 0);                   // 6
    k_combine<<<(n + 255) / 256, 256>>>(W2, b1, n);              // 7
    k_gather<<<(n4 + 255) / 256, 256>>>(n, 1);                   // 8
    k_final<<<(n + 127) / 128, 128>>>(b2, w_ih, b_ih, b_hh, Wfc, bfc, out, n); // 9
}

// round 15
// speedup vs baseline: 1.0374x; 1.0374x over previous
#include <cuda_runtime.h>
#include <cuda_fp16.h>

#define MAXN 200000
#define MAXE 6500000

// Scratch (device globals — no runtime allocation allowed)
// g_cnt zero on first call (static init); re-zeroed by k_final every call.
__device__ int      g_cnt[MAXN];        // in-degree (without self loop)
__device__ int      g_rowptr[MAXN];     // CSR row start
__device__ int      g_bsums[256];       // block sums for scan
__device__ int      g_csr[MAXE];        // src indices grouped by dst (compact)
__device__ unsigned g_rankpack[MAXE];   // (rank << 18) | dst per edge
__device__ float    g_dinv[MAXN];
__device__ __half   g_hs1h[MAXN * 16];  // layer-1 scaled features (fp16)
__device__ __half   g_hs2h[MAXN * 16];  // layer-2 scaled features (fp16)
__device__ float4   g_t1[MAXN * 4];     // layer-1 neighbor sums (fp32)
__device__ float4   g_t2[MAXN * 4];     // layer-2 neighbor sums

// ---------------------------------------------------------------------------
// count: cnt[dst]++ per edge; rank (atomic return) packed with dst, stored
// as uint4. 8 edges per thread (2x int4 loads) for MLP.
// ---------------------------------------------------------------------------
__global__ void k_count(const int* __restrict__ dst, int E) {
    int t = threadIdx.x;
    const int4* d4 = (const int4*)dst;
    int nv4 = E >> 2;
#pragma unroll
    for (int q = 0; q < 2; q++) {
        int i4 = blockIdx.x * 512 + q * 256 + t;
        if (i4 < nv4) {
            int4 v = __ldg(d4 + i4);
            int r0 = atomicAdd(&g_cnt[v.x], 1);
            int r1 = atomicAdd(&g_cnt[v.y], 1);
            int r2 = atomicAdd(&g_cnt[v.z], 1);
            int r3 = atomicAdd(&g_cnt[v.w], 1);
            uint4 p;
            p.x = ((unsigned)r0 << 18) | (unsigned)v.x;
            p.y = ((unsigned)r1 << 18) | (unsigned)v.y;
            p.z = ((unsigned)r2 << 18) | (unsigned)v.z;
            p.w = ((unsigned)r3 << 18) | (unsigned)v.w;
            ((uint4*)g_rankpack)[i4] = p;
        }
    }
    if (blockIdx.x == 0 && t < (E & 3)) {
        int e = nv4 * 4 + t;
        int d = __ldg(dst + e);
        int r = atomicAdd(&g_cnt[d], 1);
        g_rankpack[e] = ((unsigned)r << 18) | (unsigned)d;
    }
}

// scan part 1: per-block (1024 elements) sums
__global__ void k_scan1(int n) {
    __shared__ int sh[256];
    int b = blockIdx.x, t = threadIdx.x;
    int i0 = b * 1024 + t * 4;
    int s = 0;
#pragma unroll
    for (int k = 0; k < 4; k++) { int i = i0 + k; if (i < n) s += g_cnt[i]; }
    sh[t] = s; __syncthreads();
    for (int off = 128; off > 0; off >>= 1) {
        if (t < off) sh[t] += sh[t + off];
        __syncthreads();
    }
    if (t == 0) g_bsums[b] = sh[0];
}

// scan part 2: every block redundantly scans block sums, then its chunk;
// also writes dinv.
__global__ void k_scan23(int n, int nb) {
    __shared__ int bs[256];
    __shared__ int sh[256];
    int b = blockIdx.x, t = threadIdx.x;

    int v = (t < nb) ? g_bsums[t] : 0;
    bs[t] = v; __syncthreads();
    for (int off = 1; off < 256; off <<= 1) {
        int a = (t >= off) ? bs[t - off] : 0;
        __syncthreads();
        bs[t] += a;
        __syncthreads();
    }
    int blockoff = (b > 0) ? bs[b - 1] : 0;

    int i0 = b * 1024 + t * 4;
    int c[4]; int s = 0;
#pragma unroll
    for (int k = 0; k < 4; k++) { int i = i0 + k; c[k] = (i < n) ? g_cnt[i] : 0; s += c[k]; }
    int tot = s;
    sh[t] = tot; __syncthreads();
    for (int off = 1; off < 256; off <<= 1) {
        int a = (t >= off) ? sh[t - off] : 0;
        __syncthreads();
        sh[t] += a;
        __syncthreads();
    }
    int run = sh[t] - tot + blockoff;
#pragma unroll
    for (int k = 0; k < 4; k++) {
        int i = i0 + k;
        if (i < n) {
            g_rowptr[i] = run; run += c[k];
            g_dinv[i] = rsqrtf((float)c[k] + 1.0f);
        }
    }
}

// ---------------------------------------------------------------------------
// GEMM1: 2 nodes per thread -> each smem W load feeds 2 FMA chains (LDS/node
// halved, ILP doubled). hs1 = (x @ W1) * dinv -> fp16. 8KB smem.
// Block covers 512 nodes with 256 threads: thread t -> nodes base+t, base+256+t.
// ---------------------------------------------------------------------------
__global__ void k_gemm(const float* __restrict__ x, const float* __restrict__ W1, int n) {
    __shared__ float4 Ws[512];            // W1: 128x16 f32 = 8KB
    int t = threadIdx.x;                  // 256 threads

    {
        const float4* W4 = (const float4*)W1;
        for (int i = t; i < 512; i += 256) Ws[i] = W4[i];
    }
    __syncthreads();

    int base = blockIdx.x * 512;
    int na = base + t;
    int nb = base + 256 + t;
    bool vA = na < n;
    bool vB = nb < n;
    if (!vA) return;                      // nb > na, so nothing to do

    const float4* xa = (const float4*)x + (size_t)na * 32;
    const float4* xb = (const float4*)x + (size_t)nb * 32;

    float accA[16], accB[16];
#pragma unroll
    for (int q = 0; q < 16; q++) { accA[q] = 0.f; accB[q] = 0.f; }

    float4 zero4 = make_float4(0.f, 0.f, 0.f, 0.f);
#pragma unroll 4
    for (int k4 = 0; k4 < 32; k4++) {
        float4 va = __ldg(xa + k4);
        float4 vb = vB ? __ldg(xb + k4) : zero4;
        float aj[4] = {va.x, va.y, va.z, va.w};
        float bj[4] = {vb.x, vb.y, vb.z, vb.w};
#pragma unroll
        for (int j = 0; j < 4; j++) {
            int k = k4 * 4 + j;
            float4 w0 = Ws[k * 4 + 0];
            float4 w1 = Ws[k * 4 + 1];
            float4 w2 = Ws[k * 4 + 2];
            float4 w3 = Ws[k * 4 + 3];
            float a = aj[j], b = bj[j];
            accA[0]  += a * w0.x; accA[1]  += a * w0.y; accA[2]  += a * w0.z; accA[3]  += a * w0.w;
            accB[0]  += b * w0.x; accB[1]  += b * w0.y; accB[2]  += b * w0.z; accB[3]  += b * w0.w;
            accA[4]  += a * w1.x; accA[5]  += a * w1.y; accA[6]  += a * w1.z; accA[7]  += a * w1.w;
            accB[4]  += b * w1.x; accB[5]  += b * w1.y; accB[6]  += b * w1.z; accB[7]  += b * w1.w;
            accA[8]  += a * w2.x; accA[9]  += a * w2.y; accA[10] += a * w2.z; accA[11] += a * w2.w;
            accB[8]  += b * w2.x; accB[9]  += b * w2.y; accB[10] += b * w2.z; accB[11] += b * w2.w;
            accA[12] += a * w3.x; accA[13] += a * w3.y; accA[14] += a * w3.z; accA[15] += a * w3.w;
            accB[12] += b * w3.x; accB[13] += b * w3.y; accB[14] += b * w3.z; accB[15] += b * w3.w;
        }
    }
    {
        float di = g_dinv[na];
        __half2* o = (__half2*)(g_hs1h + na * 16);
#pragma unroll
        for (int q = 0; q < 8; q++)
            o[q] = __float22half2_rn(make_float2(accA[2 * q] * di, accA[2 * q + 1] * di));
    }
    if (vB) {
        float di = g_dinv[nb];
        __half2* o = (__half2*)(g_hs1h + nb * 16);
#pragma unroll
        for (int q = 0; q < 8; q++)
            o[q] = __float22half2_rn(make_float2(accB[2 * q] * di, accB[2 * q + 1] * di));
    }
}

// ---------------------------------------------------------------------------
// fill: pos = rowptr[d] + rank  (NO atomics, low regs, high occupancy)
// ---------------------------------------------------------------------------
__global__ void k_fill(const int* __restrict__ src, int E) {
    int e = blockIdx.x * blockDim.x + threadIdx.x;
    if (e >= E) return;
    unsigned code = g_rankpack[e];
    int d = (int)(code & 0x3FFFFu);
    int rank = (int)(code >> 18);
    int pos = __ldg(g_rowptr + d) + rank;
    g_csr[pos] = __ldg(src + e);
}

// ---------------------------------------------------------------------------
// gather pass: 4 threads per node, 4 channels each via uint2, 8-deep batching.
// ---------------------------------------------------------------------------
__global__ void k_gather(int n, int layer) {
    int gid = blockIdx.x * blockDim.x + threadIdx.x;
    int node = gid >> 2;
    int sub  = gid & 3;
    if (node >= n) return;
    const uint2* hs = (const uint2*)(layer ? g_hs2h : g_hs1h);
    float4* tt = layer ? g_t2 : g_t1;

    int row = g_rowptr[node];
    int cnt = g_cnt[node];
    const int* cs = g_csr + row;

    float a0 = 0.f, a1 = 0.f, a2 = 0.f, a3 = 0.f;
    int j = 0;
    for (; j + 8 <= cnt; j += 8) {
        int s[8];
#pragma unroll
        for (int q = 0; q < 8; q++) s[q] = __ldg(cs + j + q);
        uint2 u[8];
#pragma unroll
        for (int q = 0; q < 8; q++) u[q] = __ldg(hs + s[q] * 4 + sub);
#pragma unroll
        for (int q = 0; q < 8; q++) {
            float2 f = __half22float2(*(const __half2*)&u[q].x);
            float2 g = __half22float2(*(const __half2*)&u[q].y);
            a0 += f.x; a1 += f.y; a2 += g.x; a3 += g.y;
        }
    }
    for (; j < cnt; j++) {
        int s = __ldg(cs + j);
        uint2 u = __ldg(hs + s * 4 + sub);
        float2 f = __half22float2(*(const __half2*)&u.x);
        float2 g = __half22float2(*(const __half2*)&u.y);
        a0 += f.x; a1 += f.y; a2 += g.x; a3 += g.y;
    }
    tt[node * 4 + sub] = make_float4(a0, a1, a2, a3);
}

// ---------------------------------------------------------------------------
// combine: h1 = relu(dinv*(t1+hs1)+b1); hs2 = (h1 @ W2)*dinv -> fp16.
// ---------------------------------------------------------------------------
__global__ void k_combine(const float* __restrict__ W2, const float* __restrict__ b1, int n) {
    __shared__ float W2s[256];
    __shared__ float b1s[16];
    int t = threadIdx.x;
    if (t < 256) W2s[t] = W2[t];
    if (t < 16)  b1s[t] = b1[t];
    __syncthreads();

    int i = blockIdx.x * blockDim.x + threadIdx.x;
    if (i >= n) return;
    float di = g_dinv[i];

    float h1[16];
#pragma unroll
    for (int q = 0; q < 4; q++) {
        float4 tv = g_t1[i * 4 + q];
        float2 s0 = __half22float2(((const __half2*)g_hs1h)[i * 8 + q * 2 + 0]);
        float2 s1 = __half22float2(((const __half2*)g_hs1h)[i * 8 + q * 2 + 1]);
        float v;
        v = di * (tv.x + s0.x) + b1s[q * 4 + 0]; h1[q * 4 + 0] = v > 0.f ? v : 0.f;
        v = di * (tv.y + s0.y) + b1s[q * 4 + 1]; h1[q * 4 + 1] = v > 0.f ? v : 0.f;
        v = di * (tv.z + s1.x) + b1s[q * 4 + 2]; h1[q * 4 + 2] = v > 0.f ? v : 0.f;
        v = di * (tv.w + s1.y) + b1s[q * 4 + 3]; h1[q * 4 + 3] = v > 0.f ? v : 0.f;
    }
#pragma unroll
    for (int q = 0; q < 4; q++) {
        float a0 = 0.f, a1 = 0.f, a2 = 0.f, a3 = 0.f;
#pragma unroll
        for (int k = 0; k < 16; k++) {
            float hv = h1[k];
            a0 += hv * W2s[k * 16 + q * 4 + 0];
            a1 += hv * W2s[k * 16 + q * 4 + 1];
            a2 += hv * W2s[k * 16 + q * 4 + 2];
            a3 += hv * W2s[k * 16 + q * 4 + 3];
        }
        ((__half2*)g_hs2h)[i * 8 + q * 2 + 0] = __float22half2_rn(make_float2(a0 * di, a1 * di));
        ((__half2*)g_hs2h)[i * 8 + q * 2 + 1] = __float22half2_rn(make_float2(a2 * di, a3 * di));
    }
}

// ---------------------------------------------------------------------------
// final: h2 = relu(dinv*(t2+hs2)+b2); GRU (h0=0 => gh=b_hh); out = h'@Wfc.T+bfc
// Also re-zeroes g_cnt for the next kernel_launch call.
// ---------------------------------------------------------------------------
__device__ __forceinline__ float sigmoidf_(float x) { return 1.0f / (1.0f + expf(-x)); }

__global__ void k_final(const float* __restrict__ b2,
                        const float* __restrict__ w_ih, const float* __restrict__ b_ih,
                        const float* __restrict__ b_hh,
                        const float* __restrict__ Wfc, const float* __restrict__ bfc,
                        float* __restrict__ out, int n) {
    __shared__ float wihs[768];
    __shared__ float wfcs[512];
    __shared__ float bihs[48];
    __shared__ float bhhs[48];
    __shared__ float bfcs[32];
    __shared__ float b2s[16];
    int t = threadIdx.x;
    for (int i = t; i < 768; i += blockDim.x) wihs[i] = w_ih[i];
    for (int i = t; i < 512; i += blockDim.x) wfcs[i] = Wfc[i];
    if (t < 48) { bihs[t] = b_ih[t]; bhhs[t] = b_hh[t]; }
    if (t < 32) bfcs[t] = bfc[t];
    if (t < 16) b2s[t] = b2[t];
    __syncthreads();

    int i = blockIdx.x * blockDim.x + threadIdx.x;
    if (i >= n) return;
    g_cnt[i] = 0;                      // reset for next call
    float di = g_dinv[i];

    float h2[16];
#pragma unroll
    for (int q = 0; q < 4; q++) {
        float4 tv = g_t2[i * 4 + q];
        float2 s0 = __half22float2(((const __half2*)g_hs2h)[i * 8 + q * 2 + 0]);
        float2 s1 = __half22float2(((const __half2*)g_hs2h)[i * 8 + q * 2 + 1]);
        float v;
        v = di * (tv.x + s0.x) + b2s[q * 4 + 0]; h2[q * 4 + 0] = v > 0.f ? v : 0.f;
        v = di * (tv.y + s0.y) + b2s[q * 4 + 1]; h2[q * 4 + 1] = v > 0.f ? v : 0.f;
        v = di * (tv.z + s1.x) + b2s[q * 4 + 2]; h2[q * 4 + 2] = v > 0.f ? v : 0.f;
        v = di * (tv.w + s1.y) + b2s[q * 4 + 3]; h2[q * 4 + 3] = v > 0.f ? v : 0.f;
    }

    float hout[16];
#pragma unroll
    for (int k = 0; k < 16; k++) {
        float ar = bihs[k], az = bihs[16 + k], an = bihs[32 + k];
#pragma unroll
        for (int c = 0; c < 16; c++) {
            float hv = h2[c];
            ar += hv * wihs[k * 16 + c];
            az += hv * wihs[(16 + k) * 16 + c];
            an += hv * wihs[(32 + k) * 16 + c];
        }
        float r = sigmoidf_(ar + bhhs[k]);
        float z = sigmoidf_(az + bhhs[16 + k]);
        float nn = tanhf(an + r * bhhs[32 + k]);
        hout[k] = (1.0f - z) * nn;
    }

    float4* outp = (float4*)(out + (size_t)i * 32);
#pragma unroll
    for (int q = 0; q < 8; q++) {
        float4 o;
        float a0 = bfcs[q * 4 + 0], a1 = bfcs[q * 4 + 1];
        float a2 = bfcs[q * 4 + 2], a3 = bfcs[q * 4 + 3];
#pragma unroll
        for (int k = 0; k < 16; k++) {
            float hv = hout[k];
            a0 += hv * wfcs[(q * 4 + 0) * 16 + k];
            a1 += hv * wfcs[(q * 4 + 1) * 16 + k];
            a2 += hv * wfcs[(q * 4 + 2) * 16 + k];
            a3 += hv * wfcs[(q * 4 + 3) * 16 + k];
        }
        o.x = a0; o.y = a1; o.z = a2; o.w = a3;
        outp[q] = o;
    }
}

// ---------------------------------------------------------------------------
extern "C" void kernel_launch(void* const* d_in, const int* in_sizes, int n_in,
                              void* d_out, int out_size) {
    const float* x    = (const float*)d_in[0];
    const int*   ei   = (const int*)  d_in[1];
    const float* W1   = (const float*)d_in[3];
    const float* b1   = (const float*)d_in[4];
    const float* W2   = (const float*)d_in[5];
    const float* b2   = (const float*)d_in[6];
    const float* w_ih = (const float*)d_in[7];
    const float* b_ih = (const float*)d_in[9];
    const float* b_hh = (const float*)d_in[10];
    const float* Wfc  = (const float*)d_in[11];
    const float* bfc  = (const float*)d_in[12];
    float* out = (float*)d_out;

    int n = in_sizes[2];           // N nodes
    int E = in_sizes[1] / 2;       // edges
    const int* src = ei;
    const int* dst = ei + E;

    int nv4 = E >> 2;
    int ncount = (nv4 + 511) / 512;
    int nb     = (n + 1023) / 1024;          // scan blocks (<=256)
    int ngemm  = (n + 511) / 512;            // 512 nodes per block

    k_count<<<ncount, 256>>>(dst, E);                            // 1
    k_scan1<<<nb, 256>>>(n);                                     // 2
    k_scan23<<<nb, 256>>>(n, nb);                                // 3
    k_gemm<<<ngemm, 256>>>(x, W1, n);                            // 4: PROFILED
    k_fill<<<(E + 255) / 256, 256>>>(src, E);                    // 5

    int n4 = n * 4;
    k_gather<<<(n4 + 255) / 256, 256>>>(n, 0);                   // 6
    k_combine<<<(n + 255) / 256, 256>>>(W2, b1, n);              // 7
    k_gather<<<(n4 + 255) / 256, 256>>>(n, 1);                   // 8
    k_final<<<(n + 127) / 128, 128>>>(b2, w_ih, b_ih, b_hh, Wfc, bfc, out, n); // 9
}

// round 16
// speedup vs baseline: 1.0456x; 1.0079x over previous
#include <cuda_runtime.h>
#include <cuda_fp16.h>

#define MAXN 200000
#define MAXE 7100000   // E + 3N padding (rows aligned to 4 ints)

// Scratch (device globals — no runtime allocation allowed)
// g_cnt zero on first call (static init); re-zeroed by k_final every call.
__device__ int      g_cnt[MAXN];        // in-degree (without self loop)
__device__ int      g_rowptr[MAXN];     // CSR row start (4-int aligned)
__device__ int      g_bsums[256];       // block sums for scan
__device__ int      g_csr[MAXE];        // src indices grouped by dst (padded rows)
__device__ unsigned g_rankpack[MAXE];   // (rank << 18) | dst per edge
__device__ float    g_dinv[MAXN];
__device__ __half   g_hs1h[MAXN * 16];  // layer-1 scaled features (fp16)
__device__ __half   g_hs2h[MAXN * 16];  // layer-2 scaled features (fp16)
__device__ float4   g_t1[MAXN * 4];     // layer-1 neighbor sums (fp32)
__device__ float4   g_t2[MAXN * 4];     // layer-2 neighbor sums

// ---------------------------------------------------------------------------
// count: cnt[dst]++ per edge; rank (atomic return) packed with dst, stored
// as uint4. 8 edges per thread (2x int4 loads) for MLP.
// ---------------------------------------------------------------------------
__global__ void k_count(const int* __restrict__ dst, int E) {
    int t = threadIdx.x;
    const int4* d4 = (const int4*)dst;
    int nv4 = E >> 2;
#pragma unroll
    for (int q = 0; q < 2; q++) {
        int i4 = blockIdx.x * 512 + q * 256 + t;
        if (i4 < nv4) {
            int4 v = __ldg(d4 + i4);
            int r0 = atomicAdd(&g_cnt[v.x], 1);
            int r1 = atomicAdd(&g_cnt[v.y], 1);
            int r2 = atomicAdd(&g_cnt[v.z], 1);
            int r3 = atomicAdd(&g_cnt[v.w], 1);
            uint4 p;
            p.x = ((unsigned)r0 << 18) | (unsigned)v.x;
            p.y = ((unsigned)r1 << 18) | (unsigned)v.y;
            p.z = ((unsigned)r2 << 18) | (unsigned)v.z;
            p.w = ((unsigned)r3 << 18) | (unsigned)v.w;
            ((uint4*)g_rankpack)[i4] = p;
        }
    }
    if (blockIdx.x == 0 && t < (E & 3)) {
        int e = nv4 * 4 + t;
        int d = __ldg(dst + e);
        int r = atomicAdd(&g_cnt[d], 1);
        g_rankpack[e] = ((unsigned)r << 18) | (unsigned)d;
    }
}

// scan part 1: per-block (1024 elements) sums of PADDED counts
__global__ void k_scan1(int n) {
    __shared__ int sh[256];
    int b = blockIdx.x, t = threadIdx.x;
    int i0 = b * 1024 + t * 4;
    int s = 0;
#pragma unroll
    for (int k = 0; k < 4; k++) {
        int i = i0 + k;
        if (i < n) s += (g_cnt[i] + 3) & ~3;
    }
    sh[t] = s; __syncthreads();
    for (int off = 128; off > 0; off >>= 1) {
        if (t < off) sh[t] += sh[t + off];
        __syncthreads();
    }
    if (t == 0) g_bsums[b] = sh[0];
}

// scan part 2: every block redundantly scans block sums, then its chunk
// (padded counts); also writes dinv.
__global__ void k_scan23(int n, int nb) {
    __shared__ int bs[256];
    __shared__ int sh[256];
    int b = blockIdx.x, t = threadIdx.x;

    int v = (t < nb) ? g_bsums[t] : 0;
    bs[t] = v; __syncthreads();
    for (int off = 1; off < 256; off <<= 1) {
        int a = (t >= off) ? bs[t - off] : 0;
        __syncthreads();
        bs[t] += a;
        __syncthreads();
    }
    int blockoff = (b > 0) ? bs[b - 1] : 0;

    int i0 = b * 1024 + t * 4;
    int c[4], p[4]; int s = 0;
#pragma unroll
    for (int k = 0; k < 4; k++) {
        int i = i0 + k;
        c[k] = (i < n) ? g_cnt[i] : 0;
        p[k] = (c[k] + 3) & ~3;
        s += p[k];
    }
    int tot = s;
    sh[t] = tot; __syncthreads();
    for (int off = 1; off < 256; off <<= 1) {
        int a = (t >= off) ? sh[t - off] : 0;
        __syncthreads();
        sh[t] += a;
        __syncthreads();
    }
    int run = sh[t] - tot + blockoff;
#pragma unroll
    for (int k = 0; k < 4; k++) {
        int i = i0 + k;
        if (i < n) {
            g_rowptr[i] = run; run += p[k];
            g_dinv[i] = rsqrtf((float)c[k] + 1.0f);
        }
    }
}

// ---------------------------------------------------------------------------
// GEMM1: 2 nodes per thread -> each smem W load feeds 2 FMA chains.
// hs1 = (x @ W1) * dinv -> fp16. 8KB smem.
// ---------------------------------------------------------------------------
__global__ void k_gemm(const float* __restrict__ x, const float* __restrict__ W1, int n) {
    __shared__ float4 Ws[512];            // W1: 128x16 f32 = 8KB
    int t = threadIdx.x;                  // 256 threads

    {
        const float4* W4 = (const float4*)W1;
        for (int i = t; i < 512; i += 256) Ws[i] = W4[i];
    }
    __syncthreads();

    int base = blockIdx.x * 512;
    int na = base + t;
    int nb = base + 256 + t;
    bool vA = na < n;
    bool vB = nb < n;
    if (!vA) return;

    const float4* xa = (const float4*)x + (size_t)na * 32;
    const float4* xb = (const float4*)x + (size_t)nb * 32;

    float accA[16], accB[16];
#pragma unroll
    for (int q = 0; q < 16; q++) { accA[q] = 0.f; accB[q] = 0.f; }

    float4 zero4 = make_float4(0.f, 0.f, 0.f, 0.f);
#pragma unroll 4
    for (int k4 = 0; k4 < 32; k4++) {
        float4 va = __ldg(xa + k4);
        float4 vb = vB ? __ldg(xb + k4) : zero4;
        float aj[4] = {va.x, va.y, va.z, va.w};
        float bj[4] = {vb.x, vb.y, vb.z, vb.w};
#pragma unroll
        for (int j = 0; j < 4; j++) {
            int k = k4 * 4 + j;
            float4 w0 = Ws[k * 4 + 0];
            float4 w1 = Ws[k * 4 + 1];
            float4 w2 = Ws[k * 4 + 2];
            float4 w3 = Ws[k * 4 + 3];
            float a = aj[j], b = bj[j];
            accA[0]  += a * w0.x; accA[1]  += a * w0.y; accA[2]  += a * w0.z; accA[3]  += a * w0.w;
            accB[0]  += b * w0.x; accB[1]  += b * w0.y; accB[2]  += b * w0.z; accB[3]  += b * w0.w;
            accA[4]  += a * w1.x; accA[5]  += a * w1.y; accA[6]  += a * w1.z; accA[7]  += a * w1.w;
            accB[4]  += b * w1.x; accB[5]  += b * w1.y; accB[6]  += b * w1.z; accB[7]  += b * w1.w;
            accA[8]  += a * w2.x; accA[9]  += a * w2.y; accA[10] += a * w2.z; accA[11] += a * w2.w;
            accB[8]  += b * w2.x; accB[9]  += b * w2.y; accB[10] += b * w2.z; accB[11] += b * w2.w;
            accA[12] += a * w3.x; accA[13] += a * w3.y; accA[14] += a * w3.z; accA[15] += a * w3.w;
            accB[12] += b * w3.x; accB[13] += b * w3.y; accB[14] += b * w3.z; accB[15] += b * w3.w;
        }
    }
    {
        float di = g_dinv[na];
        __half2* o = (__half2*)(g_hs1h + na * 16);
#pragma unroll
        for (int q = 0; q < 8; q++)
            o[q] = __float22half2_rn(make_float2(accA[2 * q] * di, accA[2 * q + 1] * di));
    }
    if (vB) {
        float di = g_dinv[nb];
        __half2* o = (__half2*)(g_hs1h + nb * 16);
#pragma unroll
        for (int q = 0; q < 8; q++)
            o[q] = __float22half2_rn(make_float2(accB[2 * q] * di, accB[2 * q + 1] * di));
    }
}

// ---------------------------------------------------------------------------
// fill: pos = rowptr[d] + rank  (NO atomics, low regs, high occupancy)
// ---------------------------------------------------------------------------
__global__ void k_fill(const int* __restrict__ src, int E) {
    int e = blockIdx.x * blockDim.x + threadIdx.x;
    if (e >= E) return;
    unsigned code = g_rankpack[e];
    int d = (int)(code & 0x3FFFFu);
    int rank = (int)(code >> 18);
    int pos = __ldg(g_rowptr + d) + rank;
    g_csr[pos] = __ldg(src + e);
}

// ---------------------------------------------------------------------------
// gather: 4 threads/node, 4 channels each. Indices loaded via BROADCAST int4
// (all 4 lanes, same 16B address -> 1 wavefront, no shuffles). Rows 16B-aligned
// by the padded scan. 8-deep feature batching for MLP.
// ---------------------------------------------------------------------------
__global__ void k_gather(int n, int layer) {
    int gid = blockIdx.x * blockDim.x + threadIdx.x;
    int node = gid >> 2;
    int sub  = gid & 3;
    if (node >= n) return;
    const uint2* hs = (const uint2*)(layer ? g_hs2h : g_hs1h);
    float4* tt = layer ? g_t2 : g_t1;

    int row = g_rowptr[node];
    int cnt = g_cnt[node];
    const int* cs = g_csr + row;

    float a0 = 0.f, a1 = 0.f, a2 = 0.f, a3 = 0.f;
    int j = 0;
    for (; j + 8 <= cnt; j += 8) {
        int4 i0 = __ldg((const int4*)(cs + j));        // broadcast across quad
        int4 i1 = __ldg((const int4*)(cs + j + 4));
        uint2 u[8];
        u[0] = __ldg(hs + i0.x * 4 + sub);
        u[1] = __ldg(hs + i0.y * 4 + sub);
        u[2] = __ldg(hs + i0.z * 4 + sub);
        u[3] = __ldg(hs + i0.w * 4 + sub);
        u[4] = __ldg(hs + i1.x * 4 + sub);
        u[5] = __ldg(hs + i1.y * 4 + sub);
        u[6] = __ldg(hs + i1.z * 4 + sub);
        u[7] = __ldg(hs + i1.w * 4 + sub);
#pragma unroll
        for (int q = 0; q < 8; q++) {
            float2 f = __half22float2(*(const __half2*)&u[q].x);
            float2 g = __half22float2(*(const __half2*)&u[q].y);
            a0 += f.x; a1 += f.y; a2 += g.x; a3 += g.y;
        }
    }
    if (j + 4 <= cnt) {
        int4 i0 = __ldg((const int4*)(cs + j));
        uint2 u[4];
        u[0] = __ldg(hs + i0.x * 4 + sub);
        u[1] = __ldg(hs + i0.y * 4 + sub);
        u[2] = __ldg(hs + i0.z * 4 + sub);
        u[3] = __ldg(hs + i0.w * 4 + sub);
#pragma unroll
        for (int q = 0; q < 4; q++) {
            float2 f = __half22float2(*(const __half2*)&u[q].x);
            float2 g = __half22float2(*(const __half2*)&u[q].y);
            a0 += f.x; a1 += f.y; a2 += g.x; a3 += g.y;
        }
        j += 4;
    }
    for (; j < cnt; j++) {
        int s = __ldg(cs + j);
        uint2 u = __ldg(hs + s * 4 + sub);
        float2 f = __half22float2(*(const __half2*)&u.x);
        float2 g = __half22float2(*(const __half2*)&u.y);
        a0 += f.x; a1 += f.y; a2 += g.x; a3 += g.y;
    }
    tt[node * 4 + sub] = make_float4(a0, a1, a2, a3);
}

// ---------------------------------------------------------------------------
// combine: h1 = relu(dinv*(t1+hs1)+b1); hs2 = (h1 @ W2)*dinv -> fp16.
// ---------------------------------------------------------------------------
__global__ void k_combine(const float* __restrict__ W2, const float* __restrict__ b1, int n) {
    __shared__ float W2s[256];
    __shared__ float b1s[16];
    int t = threadIdx.x;
    if (t < 256) W2s[t] = W2[t];
    if (t < 16)  b1s[t] = b1[t];
    __syncthreads();

    int i = blockIdx.x * blockDim.x + threadIdx.x;
    if (i >= n) return;
    float di = g_dinv[i];

    float h1[16];
#pragma unroll
    for (int q = 0; q < 4; q++) {
        float4 tv = g_t1[i * 4 + q];
        float2 s0 = __half22float2(((const __half2*)g_hs1h)[i * 8 + q * 2 + 0]);
        float2 s1 = __half22float2(((const __half2*)g_hs1h)[i * 8 + q * 2 + 1]);
        float v;
        v = di * (tv.x + s0.x) + b1s[q * 4 + 0]; h1[q * 4 + 0] = v > 0.f ? v : 0.f;
        v = di * (tv.y + s0.y) + b1s[q * 4 + 1]; h1[q * 4 + 1] = v > 0.f ? v : 0.f;
        v = di * (tv.z + s1.x) + b1s[q * 4 + 2]; h1[q * 4 + 2] = v > 0.f ? v : 0.f;
        v = di * (tv.w + s1.y) + b1s[q * 4 + 3]; h1[q * 4 + 3] = v > 0.f ? v : 0.f;
    }
#pragma unroll
    for (int q = 0; q < 4; q++) {
        float a0 = 0.f, a1 = 0.f, a2 = 0.f, a3 = 0.f;
#pragma unroll
        for (int k = 0; k < 16; k++) {
            float hv = h1[k];
            a0 += hv * W2s[k * 16 + q * 4 + 0];
            a1 += hv * W2s[k * 16 + q * 4 + 1];
            a2 += hv * W2s[k * 16 + q * 4 + 2];
            a3 += hv * W2s[k * 16 + q * 4 + 3];
        }
        ((__half2*)g_hs2h)[i * 8 + q * 2 + 0] = __float22half2_rn(make_float2(a0 * di, a1 * di));
        ((__half2*)g_hs2h)[i * 8 + q * 2 + 1] = __float22half2_rn(make_float2(a2 * di, a3 * di));
    }
}

// ---------------------------------------------------------------------------
// final: h2 = relu(dinv*(t2+hs2)+b2); GRU (h0=0 => gh=b_hh); out = h'@Wfc.T+bfc
// Also re-zeroes g_cnt for the next kernel_launch call.
// ---------------------------------------------------------------------------
__device__ __forceinline__ float sigmoidf_(float x) { return 1.0f / (1.0f + expf(-x)); }

__global__ void k_final(const float* __restrict__ b2,
                        const float* __restrict__ w_ih, const float* __restrict__ b_ih,
                        const float* __restrict__ b_hh,
                        const float* __restrict__ Wfc, const float* __restrict__ bfc,
                        float* __restrict__ out, int n) {
    __shared__ float wihs[768];
    __shared__ float wfcs[512];
    __shared__ float bihs[48];
    __shared__ float bhhs[48];
    __shared__ float bfcs[32];
    __shared__ float b2s[16];
    int t = threadIdx.x;
    for (int i = t; i < 768; i += blockDim.x) wihs[i] = w_ih[i];
    for (int i = t; i < 512; i += blockDim.x) wfcs[i] = Wfc[i];
    if (t < 48) { bihs[t] = b_ih[t]; bhhs[t] = b_hh[t]; }
    if (t < 32) bfcs[t] = bfc[t];
    if (t < 16) b2s[t] = b2[t];
    __syncthreads();

    int i = blockIdx.x * blockDim.x + threadIdx.x;
    if (i >= n) return;
    g_cnt[i] = 0;                      // reset for next call
    float di = g_dinv[i];

    float h2[16];
#pragma unroll
    for (int q = 0; q < 4; q++) {
        float4 tv = g_t2[i * 4 + q];
        float2 s0 = __half22float2(((const __half2*)g_hs2h)[i * 8 + q * 2 + 0]);
        float2 s1 = __half22float2(((const __half2*)g_hs2h)[i * 8 + q * 2 + 1]);
        float v;
        v = di * (tv.x + s0.x) + b2s[q * 4 + 0]; h2[q * 4 + 0] = v > 0.f ? v : 0.f;
        v = di * (tv.y + s0.y) + b2s[q * 4 + 1]; h2[q * 4 + 1] = v > 0.f ? v : 0.f;
        v = di * (tv.z + s1.x) + b2s[q * 4 + 2]; h2[q * 4 + 2] = v > 0.f ? v : 0.f;
        v = di * (tv.w + s1.y) + b2s[q * 4 + 3]; h2[q * 4 + 3] = v > 0.f ? v : 0.f;
    }

    float hout[16];
#pragma unroll
    for (int k = 0; k < 16; k++) {
        float ar = bihs[k], az = bihs[16 + k], an = bihs[32 + k];
#pragma unroll
        for (int c = 0; c < 16; c++) {
            float hv = h2[c];
            ar += hv * wihs[k * 16 + c];
            az += hv * wihs[(16 + k) * 16 + c];
            an += hv * wihs[(32 + k) * 16 + c];
        }
        float r = sigmoidf_(ar + bhhs[k]);
        float z = sigmoidf_(az + bhhs[16 + k]);
        float nn = tanhf(an + r * bhhs[32 + k]);
        hout[k] = (1.0f - z) * nn;
    }

    float4* outp = (float4*)(out + (size_t)i * 32);
#pragma unroll
    for (int q = 0; q < 8; q++) {
        float4 o;
        float a0 = bfcs[q * 4 + 0], a1 = bfcs[q * 4 + 1];
        float a2 = bfcs[q * 4 + 2], a3 = bfcs[q * 4 + 3];
#pragma unroll
        for (int k = 0; k < 16; k++) {
            float hv = hout[k];
            a0 += hv * wfcs[(q * 4 + 0) * 16 + k];
            a1 += hv * wfcs[(q * 4 + 1) * 16 + k];
            a2 += hv * wfcs[(q * 4 + 2) * 16 + k];
            a3 += hv * wfcs[(q * 4 + 3) * 16 + k];
        }
        o.x = a0; o.y = a1; o.z = a2; o.w = a3;
        outp[q] = o;
    }
}

// ---------------------------------------------------------------------------
extern "C" void kernel_launch(void* const* d_in, const int* in_sizes, int n_in,
                              void* d_out, int out_size) {
    const float* x    = (const float*)d_in[0];
    const int*   ei   = (const int*)  d_in[1];
    const float* W1   = (const float*)d_in[3];
    const float* b1   = (const float*)d_in[4];
    const float* W2   = (const float*)d_in[5];
    const float* b2   = (const float*)d_in[6];
    const float* w_ih = (const float*)d_in[7];
    const float* b_ih = (const float*)d_in[9];
    const float* b_hh = (const float*)d_in[10];
    const float* Wfc  = (const float*)d_in[11];
    const float* bfc  = (const float*)d_in[12];
    float* out = (float*)d_out;

    int n = in_sizes[2];           // N nodes
    int E = in_sizes[1] / 2;       // edges
    const int* src = ei;
    const int* dst = ei + E;

    int nv4 = E >> 2;
    int ncount = (nv4 + 511) / 512;
    int nb     = (n + 1023) / 1024;          // scan blocks (<=256)
    int ngemm  = (n + 511) / 512;            // 512 nodes per block

    k_count<<<ncount, 256>>>(dst, E);                            // 1
    k_scan1<<<nb, 256>>>(n);                                     // 2
    k_scan23<<<nb, 256>>>(n, nb);                                // 3
    k_gemm<<<ngemm, 256>>>(x, W1, n);                            // 4: PROFILED
    k_fill<<<(E + 255) / 256, 256>>>(src, E);                    // 5

    int n4 = n * 4;
    k_gather<<<(n4 + 255) / 256, 256>>>(n, 0);                   // 6
    k_combine<<<(n + 255) / 256, 256>>>(W2, b1, n);              // 7
    k_gather<<<(n4 + 255) / 256, 256>>>(n, 1);                   // 8
    k_final<<<(n + 127) / 128, 128>>>(b2, w_ih, b_ih, b_hh, Wfc, bfc, out, n); // 9
}

// round 17
// speedup vs baseline: 1.0619x; 1.0156x over previous
#include <cuda_runtime.h>
#include <cuda_fp16.h>

#define MAXN 200000
#define MAXE 7100000   // E + 3N padding (rows aligned to 4 ints)

// Scratch (device globals — no runtime allocation allowed)
// g_cnt zero on first call (static init); re-zeroed by k_final every call.
__device__ int      g_cnt[MAXN];        // in-degree (without self loop)
__device__ int      g_rowptr[MAXN];     // CSR row start (4-int aligned)
__device__ int      g_bsums[256];       // block sums for scan
__device__ int      g_csr[MAXE];        // src indices grouped by dst (padded rows)
__device__ unsigned g_rankpack[MAXE];   // (rank << 18) | dst per edge
__device__ float    g_dinv[MAXN];
__device__ __half   g_hs1h[MAXN * 16];  // layer-1 scaled features (fp16)
__device__ __half   g_hs2h[MAXN * 16];  // layer-2 scaled features (fp16)
__device__ float4   g_t1[MAXN * 4];     // layer-1 neighbor sums (fp32)
__device__ float4   g_t2[MAXN * 4];     // layer-2 neighbor sums

// ---------------------------------------------------------------------------
// count: cnt[dst]++ per edge; rank (atomic return) packed with dst, stored
// as uint4. 8 edges per thread (2x int4 loads) for MLP.
// ---------------------------------------------------------------------------
__global__ void k_count(const int* __restrict__ dst, int E) {
    int t = threadIdx.x;
    const int4* d4 = (const int4*)dst;
    int nv4 = E >> 2;
#pragma unroll
    for (int q = 0; q < 2; q++) {
        int i4 = blockIdx.x * 512 + q * 256 + t;
        if (i4 < nv4) {
            int4 v = __ldg(d4 + i4);
            int r0 = atomicAdd(&g_cnt[v.x], 1);
            int r1 = atomicAdd(&g_cnt[v.y], 1);
            int r2 = atomicAdd(&g_cnt[v.z], 1);
            int r3 = atomicAdd(&g_cnt[v.w], 1);
            uint4 p;
            p.x = ((unsigned)r0 << 18) | (unsigned)v.x;
            p.y = ((unsigned)r1 << 18) | (unsigned)v.y;
            p.z = ((unsigned)r2 << 18) | (unsigned)v.z;
            p.w = ((unsigned)r3 << 18) | (unsigned)v.w;
            ((uint4*)g_rankpack)[i4] = p;
        }
    }
    if (blockIdx.x == 0 && t < (E & 3)) {
        int e = nv4 * 4 + t;
        int d = __ldg(dst + e);
        int r = atomicAdd(&g_cnt[d], 1);
        g_rankpack[e] = ((unsigned)r << 18) | (unsigned)d;
    }
}

// scan part 1: per-block (1024 elements) sums of PADDED counts
__global__ void k_scan1(int n) {
    __shared__ int sh[256];
    int b = blockIdx.x, t = threadIdx.x;
    int i0 = b * 1024 + t * 4;
    int s = 0;
#pragma unroll
    for (int k = 0; k < 4; k++) {
        int i = i0 + k;
        if (i < n) s += (g_cnt[i] + 3) & ~3;
    }
    sh[t] = s; __syncthreads();
    for (int off = 128; off > 0; off >>= 1) {
        if (t < off) sh[t] += sh[t + off];
        __syncthreads();
    }
    if (t == 0) g_bsums[b] = sh[0];
}

// scan part 2: every block redundantly scans block sums, then its chunk
// (padded counts); writes rowptr + dinv, and scales raw hs1 in place.
__global__ void k_scan23(int n, int nb) {
    __shared__ int bs[256];
    __shared__ int sh[256];
    int b = blockIdx.x, t = threadIdx.x;

    int v = (t < nb) ? g_bsums[t] : 0;
    bs[t] = v; __syncthreads();
    for (int off = 1; off < 256; off <<= 1) {
        int a = (t >= off) ? bs[t - off] : 0;
        __syncthreads();
        bs[t] += a;
        __syncthreads();
    }
    int blockoff = (b > 0) ? bs[b - 1] : 0;

    int i0 = b * 1024 + t * 4;
    int c[4], p[4]; int s = 0;
#pragma unroll
    for (int k = 0; k < 4; k++) {
        int i = i0 + k;
        c[k] = (i < n) ? g_cnt[i] : 0;
        p[k] = (c[k] + 3) & ~3;
        s += p[k];
    }
    int tot = s;
    sh[t] = tot; __syncthreads();
    for (int off = 1; off < 256; off <<= 1) {
        int a = (t >= off) ? sh[t - off] : 0;
        __syncthreads();
        sh[t] += a;
        __syncthreads();
    }
    int run = sh[t] - tot + blockoff;
#pragma unroll
    for (int k = 0; k < 4; k++) {
        int i = i0 + k;
        if (i < n) {
            g_rowptr[i] = run; run += p[k];
            float di = rsqrtf((float)c[k] + 1.0f);
            g_dinv[i] = di;
            // scale raw hs1 (written by the overlapped gemm) in place
            __half2* ph = (__half2*)(g_hs1h + i * 16);
#pragma unroll
            for (int q = 0; q < 8; q++) {
                float2 f = __half22float2(ph[q]);
                ph[q] = __float22half2_rn(make_float2(f.x * di, f.y * di));
            }
        }
    }
}

// ---------------------------------------------------------------------------
// GEMM1 RAW (runs on the side stream, overlapped with count/scan1):
// hs1_raw = x @ W1 -> fp16 (scaling deferred to k_scan23).
// 2 nodes per thread; 8KB smem.
// ---------------------------------------------------------------------------
__global__ void k_gemm_raw(const float* __restrict__ x, const float* __restrict__ W1, int n) {
    __shared__ float4 Ws[512];            // W1: 128x16 f32 = 8KB
    int t = threadIdx.x;                  // 256 threads

    {
        const float4* W4 = (const float4*)W1;
        for (int i = t; i < 512; i += 256) Ws[i] = W4[i];
    }
    __syncthreads();

    int base = blockIdx.x * 512;
    int na = base + t;
    int nb = base + 256 + t;
    bool vA = na < n;
    bool vB = nb < n;
    if (!vA) return;

    const float4* xa = (const float4*)x + (size_t)na * 32;
    const float4* xb = (const float4*)x + (size_t)nb * 32;

    float accA[16], accB[16];
#pragma unroll
    for (int q = 0; q < 16; q++) { accA[q] = 0.f; accB[q] = 0.f; }

    float4 zero4 = make_float4(0.f, 0.f, 0.f, 0.f);
#pragma unroll 4
    for (int k4 = 0; k4 < 32; k4++) {
        float4 va = __ldg(xa + k4);
        float4 vb = vB ? __ldg(xb + k4) : zero4;
        float aj[4] = {va.x, va.y, va.z, va.w};
        float bj[4] = {vb.x, vb.y, vb.z, vb.w};
#pragma unroll
        for (int j = 0; j < 4; j++) {
            int k = k4 * 4 + j;
            float4 w0 = Ws[k * 4 + 0];
            float4 w1 = Ws[k * 4 + 1];
            float4 w2 = Ws[k * 4 + 2];
            float4 w3 = Ws[k * 4 + 3];
            float a = aj[j], b = bj[j];
            accA[0]  += a * w0.x; accA[1]  += a * w0.y; accA[2]  += a * w0.z; accA[3]  += a * w0.w;
            accB[0]  += b * w0.x; accB[1]  += b * w0.y; accB[2]  += b * w0.z; accB[3]  += b * w0.w;
            accA[4]  += a * w1.x; accA[5]  += a * w1.y; accA[6]  += a * w1.z; accA[7]  += a * w1.w;
            accB[4]  += b * w1.x; accB[5]  += b * w1.y; accB[6]  += b * w1.z; accB[7]  += b * w1.w;
            accA[8]  += a * w2.x; accA[9]  += a * w2.y; accA[10] += a * w2.z; accA[11] += a * w2.w;
            accB[8]  += b * w2.x; accB[9]  += b * w2.y; accB[10] += b * w2.z; accB[11] += b * w2.w;
            accA[12] += a * w3.x; accA[13] += a * w3.y; accA[14] += a * w3.z; accA[15] += a * w3.w;
            accB[12] += b * w3.x; accB[13] += b * w3.y; accB[14] += b * w3.z; accB[15] += b * w3.w;
        }
    }
    {
        __half2* o = (__half2*)(g_hs1h + na * 16);
#pragma unroll
        for (int q = 0; q < 8; q++)
            o[q] = __float22half2_rn(make_float2(accA[2 * q], accA[2 * q + 1]));
    }
    if (vB) {
        __half2* o = (__half2*)(g_hs1h + nb * 16);
#pragma unroll
        for (int q = 0; q < 8; q++)
            o[q] = __float22half2_rn(make_float2(accB[2 * q], accB[2 * q + 1]));
    }
}

// ---------------------------------------------------------------------------
// fill: pos = rowptr[d] + rank  (NO atomics, low regs, high occupancy)
// ---------------------------------------------------------------------------
__global__ void k_fill(const int* __restrict__ src, int E) {
    int e = blockIdx.x * blockDim.x + threadIdx.x;
    if (e >= E) return;
    unsigned code = g_rankpack[e];
    int d = (int)(code & 0x3FFFFu);
    int rank = (int)(code >> 18);
    int pos = __ldg(g_rowptr + d) + rank;
    g_csr[pos] = __ldg(src + e);
}

// ---------------------------------------------------------------------------
// gather: 4 threads/node, 4 channels each. Indices via broadcast int4
// (rows 16B-aligned by the padded scan). 8-deep feature batching.
// ---------------------------------------------------------------------------
__global__ void k_gather(int n, int layer) {
    int gid = blockIdx.x * blockDim.x + threadIdx.x;
    int node = gid >> 2;
    int sub  = gid & 3;
    if (node >= n) return;
    const uint2* hs = (const uint2*)(layer ? g_hs2h : g_hs1h);
    float4* tt = layer ? g_t2 : g_t1;

    int row = g_rowptr[node];
    int cnt = g_cnt[node];
    const int* cs = g_csr + row;

    float a0 = 0.f, a1 = 0.f, a2 = 0.f, a3 = 0.f;
    int j = 0;
    for (; j + 8 <= cnt; j += 8) {
        int4 i0 = __ldg((const int4*)(cs + j));
        int4 i1 = __ldg((const int4*)(cs + j + 4));
        uint2 u[8];
        u[0] = __ldg(hs + i0.x * 4 + sub);
        u[1] = __ldg(hs + i0.y * 4 + sub);
        u[2] = __ldg(hs + i0.z * 4 + sub);
        u[3] = __ldg(hs + i0.w * 4 + sub);
        u[4] = __ldg(hs + i1.x * 4 + sub);
        u[5] = __ldg(hs + i1.y * 4 + sub);
        u[6] = __ldg(hs + i1.z * 4 + sub);
        u[7] = __ldg(hs + i1.w * 4 + sub);
#pragma unroll
        for (int q = 0; q < 8; q++) {
            float2 f = __half22float2(*(const __half2*)&u[q].x);
            float2 g = __half22float2(*(const __half2*)&u[q].y);
            a0 += f.x; a1 += f.y; a2 += g.x; a3 += g.y;
        }
    }
    if (j + 4 <= cnt) {
        int4 i0 = __ldg((const int4*)(cs + j));
        uint2 u[4];
        u[0] = __ldg(hs + i0.x * 4 + sub);
        u[1] = __ldg(hs + i0.y * 4 + sub);
        u[2] = __ldg(hs + i0.z * 4 + sub);
        u[3] = __ldg(hs + i0.w * 4 + sub);
#pragma unroll
        for (int q = 0; q < 4; q++) {
            float2 f = __half22float2(*(const __half2*)&u[q].x);
            float2 g = __half22float2(*(const __half2*)&u[q].y);
            a0 += f.x; a1 += f.y; a2 += g.x; a3 += g.y;
        }
        j += 4;
    }
    for (; j < cnt; j++) {
        int s = __ldg(cs + j);
        uint2 u = __ldg(hs + s * 4 + sub);
        float2 f = __half22float2(*(const __half2*)&u.x);
        float2 g = __half22float2(*(const __half2*)&u.y);
        a0 += f.x; a1 += f.y; a2 += g.x; a3 += g.y;
    }
    tt[node * 4 + sub] = make_float4(a0, a1, a2, a3);
}

// ---------------------------------------------------------------------------
// combine: h1 = relu(dinv*(t1+hs1)+b1); hs2 = (h1 @ W2)*dinv -> fp16.
// ---------------------------------------------------------------------------
__global__ void k_combine(const float* __restrict__ W2, const float* __restrict__ b1, int n) {
    __shared__ float W2s[256];
    __shared__ float b1s[16];
    int t = threadIdx.x;
    if (t < 256) W2s[t] = W2[t];
    if (t < 16)  b1s[t] = b1[t];
    __syncthreads();

    int i = blockIdx.x * blockDim.x + threadIdx.x;
    if (i >= n) return;
    float di = g_dinv[i];

    float h1[16];
#pragma unroll
    for (int q = 0; q < 4; q++) {
        float4 tv = g_t1[i * 4 + q];
        float2 s0 = __half22float2(((const __half2*)g_hs1h)[i * 8 + q * 2 + 0]);
        float2 s1 = __half22float2(((const __half2*)g_hs1h)[i * 8 + q * 2 + 1]);
        float v;
        v = di * (tv.x + s0.x) + b1s[q * 4 + 0]; h1[q * 4 + 0] = v > 0.f ? v : 0.f;
        v = di * (tv.y + s0.y) + b1s[q * 4 + 1]; h1[q * 4 + 1] = v > 0.f ? v : 0.f;
        v = di * (tv.z + s1.x) + b1s[q * 4 + 2]; h1[q * 4 + 2] = v > 0.f ? v : 0.f;
        v = di * (tv.w + s1.y) + b1s[q * 4 + 3]; h1[q * 4 + 3] = v > 0.f ? v : 0.f;
    }
#pragma unroll
    for (int q = 0; q < 4; q++) {
        float a0 = 0.f, a1 = 0.f, a2 = 0.f, a3 = 0.f;
#pragma unroll
        for (int k = 0; k < 16; k++) {
            float hv = h1[k];
            a0 += hv * W2s[k * 16 + q * 4 + 0];
            a1 += hv * W2s[k * 16 + q * 4 + 1];
            a2 += hv * W2s[k * 16 + q * 4 + 2];
            a3 += hv * W2s[k * 16 + q * 4 + 3];
        }
        ((__half2*)g_hs2h)[i * 8 + q * 2 + 0] = __float22half2_rn(make_float2(a0 * di, a1 * di));
        ((__half2*)g_hs2h)[i * 8 + q * 2 + 1] = __float22half2_rn(make_float2(a2 * di, a3 * di));
    }
}

// ---------------------------------------------------------------------------
// final: h2 = relu(dinv*(t2+hs2)+b2); GRU (h0=0 => gh=b_hh); out = h'@Wfc.T+bfc
// Also re-zeroes g_cnt for the next kernel_launch call.
// ---------------------------------------------------------------------------
__device__ __forceinline__ float sigmoidf_(float x) { return 1.0f / (1.0f + expf(-x)); }

__global__ void k_final(const float* __restrict__ b2,
                        const float* __restrict__ w_ih, const float* __restrict__ b_ih,
                        const float* __restrict__ b_hh,
                        const float* __restrict__ Wfc, const float* __restrict__ bfc,
                        float* __restrict__ out, int n) {
    __shared__ float wihs[768];
    __shared__ float wfcs[512];
    __shared__ float bihs[48];
    __shared__ float bhhs[48];
    __shared__ float bfcs[32];
    __shared__ float b2s[16];
    int t = threadIdx.x;
    for (int i = t; i < 768; i += blockDim.x) wihs[i] = w_ih[i];
    for (int i = t; i < 512; i += blockDim.x) wfcs[i] = Wfc[i];
    if (t < 48) { bihs[t] = b_ih[t]; bhhs[t] = b_hh[t]; }
    if (t < 32) bfcs[t] = bfc[t];
    if (t < 16) b2s[t] = b2[t];
    __syncthreads();

    int i = blockIdx.x * blockDim.x + threadIdx.x;
    if (i >= n) return;
    g_cnt[i] = 0;                      // reset for next call
    float di = g_dinv[i];

    float h2[16];
#pragma unroll
    for (int q = 0; q < 4; q++) {
        float4 tv = g_t2[i * 4 + q];
        float2 s0 = __half22float2(((const __half2*)g_hs2h)[i * 8 + q * 2 + 0]);
        float2 s1 = __half22float2(((const __half2*)g_hs2h)[i * 8 + q * 2 + 1]);
        float v;
        v = di * (tv.x + s0.x) + b2s[q * 4 + 0]; h2[q * 4 + 0] = v > 0.f ? v : 0.f;
        v = di * (tv.y + s0.y) + b2s[q * 4 + 1]; h2[q * 4 + 1] = v > 0.f ? v : 0.f;
        v = di * (tv.z + s1.x) + b2s[q * 4 + 2]; h2[q * 4 + 2] = v > 0.f ? v : 0.f;
        v = di * (tv.w + s1.y) + b2s[q * 4 + 3]; h2[q * 4 + 3] = v > 0.f ? v : 0.f;
    }

    float hout[16];
#pragma unroll
    for (int k = 0; k < 16; k++) {
        float ar = bihs[k], az = bihs[16 + k], an = bihs[32 + k];
#pragma unroll
        for (int c = 0; c < 16; c++) {
            float hv = h2[c];
            ar += hv * wihs[k * 16 + c];
            az += hv * wihs[(16 + k) * 16 + c];
            an += hv * wihs[(32 + k) * 16 + c];
        }
        float r = sigmoidf_(ar + bhhs[k]);
        float z = sigmoidf_(az + bhhs[16 + k]);
        float nn = tanhf(an + r * bhhs[32 + k]);
        hout[k] = (1.0f - z) * nn;
    }

    float4* outp = (float4*)(out + (size_t)i * 32);
#pragma unroll
    for (int q = 0; q < 8; q++) {
        float4 o;
        float a0 = bfcs[q * 4 + 0], a1 = bfcs[q * 4 + 1];
        float a2 = bfcs[q * 4 + 2], a3 = bfcs[q * 4 + 3];
#pragma unroll
        for (int k = 0; k < 16; k++) {
            float hv = hout[k];
            a0 += hv * wfcs[(q * 4 + 0) * 16 + k];
            a1 += hv * wfcs[(q * 4 + 1) * 16 + k];
            a2 += hv * wfcs[(q * 4 + 2) * 16 + k];
            a3 += hv * wfcs[(q * 4 + 3) * 16 + k];
        }
        o.x = a0; o.y = a1; o.z = a2; o.w = a3;
        outp[q] = o;
    }
}

// ---------------------------------------------------------------------------
extern "C" void kernel_launch(void* const* d_in, const int* in_sizes, int n_in,
                              void* d_out, int out_size) {
    const float* x    = (const float*)d_in[0];
    const int*   ei   = (const int*)  d_in[1];
    const float* W1   = (const float*)d_in[3];
    const float* b1   = (const float*)d_in[4];
    const float* W2   = (const float*)d_in[5];
    const float* b2   = (const float*)d_in[6];
    const float* w_ih = (const float*)d_in[7];
    const float* b_ih = (const float*)d_in[9];
    const float* b_hh = (const float*)d_in[10];
    const float* Wfc  = (const float*)d_in[11];
    const float* bfc  = (const float*)d_in[12];
    float* out = (float*)d_out;

    int n = in_sizes[2];           // N nodes
    int E = in_sizes[1] / 2;       // edges
    const int* src = ei;
    const int* dst = ei + E;

    int nv4 = E >> 2;
    int ncount = (nv4 + 511) / 512;
    int nb     = (n + 1023) / 1024;          // scan blocks (<=256)
    int ngemm  = (n + 511) / 512;            // 512 nodes per block

    // Side stream for the independent raw GEMM (fork/join via events is
    // graph-capturable; no syncs, no allocations of device memory).
    cudaStream_t s2;
    cudaStreamCreateWithFlags(&s2, cudaStreamNonBlocking);
    cudaEvent_t eFork, eJoin;
    cudaEventCreateWithFlags(&eFork, cudaEventDisableTiming);
    cudaEventCreateWithFlags(&eJoin, cudaEventDisableTiming);

    // fork: s2 branches off the main (captured) stream
    cudaEventRecord(eFork, 0);
    cudaStreamWaitEvent(s2, eFork, 0);
    k_gemm_raw<<<ngemm, 256, 0, s2>>>(x, W1, n);       // overlaps with count
    cudaEventRecord(eJoin, s2);

    k_count<<<ncount, 256>>>(dst, E);
    k_scan1<<<nb, 256>>>(n);
    cudaStreamWaitEvent(0, eJoin, 0);                  // join before scaling hs1
    k_scan23<<<nb, 256>>>(n, nb);                      // rowptr + dinv + scale hs1
    k_fill<<<(E + 255) / 256, 256>>>(src, E);

    int n4 = n * 4;
    k_gather<<<(n4 + 255) / 256, 256>>>(n, 0);
    k_combine<<<(n + 255) / 256, 256>>>(W2, b1, n);
    k_gather<<<(n4 + 255) / 256, 256>>>(n, 1);
    k_final<<<(n + 127) / 128, 128>>>(b2, w_ih, b_ih, b_hh, Wfc, bfc, out, n);
}